// round 11
// baseline (speedup 1.0000x reference)
#include <cuda_runtime.h>
#include <cuda_fp16.h>

// AttGCNEncoder: 2x GCNConv(relu) + single-token attention.
// softmax over length-1 axis == 1  =>  output = relu(gcn2) @ Wv + bv.
// Q/K path is dead code and skipped.
//
// R11 vs R10 (252us):
//  - k_count / k_fill vectorized: 4 edges/thread, 16B index loads (they were
//    LSU-issue-bound at 1 LDG/edge, not DRAM-bound)
//  - scan1/2/3 replaced by one decoupled-lookback scan kernel
//  - CSC segments 4-aligned so k_aggr reads col indices as aligned int4
//  - 9 launches instead of 11

#define FD 64
#define MAXN 100000
#define MAXE 3200000
#define MAXCOL (MAXE + 3 * MAXN + 16)   // segments padded to multiples of 4

__device__ int    g_deg[MAXN];        // in-degree (excluding self loop)
__device__ int    g_rowstart[MAXN];   // 4-aligned CSC row offsets
__device__ int    g_cursor[MAXN];     // fill cursors
__device__ float  g_dis[MAXN];        // deg^{-1/2} (including self loop)
__device__ __align__(16) int g_col[MAXCOL];   // src node per CSC slot
__device__ __half g_h16[MAXN * FD];   // dis-scaled linear output (fp16)
__device__ float  g_acc[MAXN * FD];   // post-aggregation activations (fp32)
__device__ unsigned long long g_bstate[1024]; // lookback: (flag<<32)|value
__device__ int    g_is64;             // 1 if edge_index is int64, else int32

typedef unsigned long long u64;

// packed f32x2 fma: acc = a*b + acc
__device__ __forceinline__ void fma2(u64& acc, u64 a, u64 b) {
    asm("fma.rn.f32x2 %0, %1, %2, %0;" : "+l"(acc) : "l"(a), "l"(b));
}
__device__ __forceinline__ float hsum2(u64 v) {
    float lo, hi;
    asm("mov.b64 {%0,%1}, %2;" : "=f"(lo), "=f"(hi) : "l"(v));
    return lo + hi;
}

// ---------------------------------------------------------------------------
// zero deg + lookback state + dtype sniff
// ---------------------------------------------------------------------------
__global__ void k_zero_sniff(const int* __restrict__ ei32, int n) {
    int i = blockIdx.x * blockDim.x + threadIdx.x;
    if (i < n) g_deg[i] = 0;
    if (i < 1024) g_bstate[i] = 0ull;
    if (i == 0) {
        int acc = 0;
#pragma unroll
        for (int j = 0; j < 16; j++) acc |= ei32[2 * j + 1];
        g_is64 = (acc == 0) ? 1 : 0;
    }
}

// ---------------------------------------------------------------------------
// k_count: 4 edges per thread, vectorized dst-row loads.
// ---------------------------------------------------------------------------
__global__ void k_count(const void* __restrict__ ei, int e, int n, int vec_ok) {
    int b = (blockIdx.x * blockDim.x + threadIdx.x) * 4;
    if (b >= e) return;
    int d[4];
    if (g_is64) {
        const long long* dst = (const long long*)ei + e;
        if (vec_ok && b + 3 < e) {
            longlong2 p0 = __ldg((const longlong2*)(dst + b));
            longlong2 p1 = __ldg((const longlong2*)(dst + b + 2));
            d[0] = (int)p0.x; d[1] = (int)p0.y; d[2] = (int)p1.x; d[3] = (int)p1.y;
        } else {
#pragma unroll
            for (int k = 0; k < 4; k++) d[k] = (b + k < e) ? (int)dst[b + k] : -1;
        }
    } else {
        const int* dst = (const int*)ei + e;
        if (vec_ok && b + 3 < e) {
            int4 p = __ldg((const int4*)(dst + b));
            d[0] = p.x; d[1] = p.y; d[2] = p.z; d[3] = p.w;
        } else {
#pragma unroll
            for (int k = 0; k < 4; k++) d[k] = (b + k < e) ? dst[b + k] : -1;
        }
    }
#pragma unroll
    for (int k = 0; k < 4; k++)
        if (b + k < e && d[k] >= 0 && d[k] < n) atomicAdd(&g_deg[d[k]], 1);
}

// ---------------------------------------------------------------------------
// Single-pass decoupled-lookback exclusive scan of ceil4(deg).
// All blocks co-resident (<=391 blocks of 256), so spin-wait is safe.
// Also emits cursor and dis.
// ---------------------------------------------------------------------------
__global__ void k_scan(int n) {
    __shared__ int s[256];
    __shared__ int s_excl;
    int t = threadIdx.x;
    int i = blockIdx.x * 256 + t;
    int deg = (i < n) ? g_deg[i] : 0;
    int v = (deg + 3) & ~3;             // padded segment length
    s[t] = v;
    __syncthreads();
#pragma unroll
    for (int off = 1; off < 256; off <<= 1) {
        int x = (t >= off) ? s[t - off] : 0;
        __syncthreads();
        s[t] += x;
        __syncthreads();
    }
    int blocksum = s[255];

    if (t == 0) {
        int excl = 0;
        if (blockIdx.x > 0) {
            atomicExch(&g_bstate[blockIdx.x],
                       (1ull << 32) | (unsigned)blocksum);   // publish aggregate
            for (int b = blockIdx.x - 1;;) {
                unsigned long long st;
                do { st = atomicAdd(&g_bstate[b], 0ull); } while ((st >> 32) == 0);
                excl += (int)(unsigned)st;
                if ((st >> 32) == 2) break;                  // inclusive prefix
                b--;
            }
        }
        atomicExch(&g_bstate[blockIdx.x],
                   (2ull << 32) | (unsigned)(excl + blocksum));
        s_excl = excl;
    }
    __syncthreads();

    if (i < n) {
        int excl_i = s_excl + s[t] - v;     // multiple of 4
        g_rowstart[i] = excl_i;
        g_cursor[i]   = excl_i;
        g_dis[i] = rsqrtf((float)(deg + 1));
    }
}

// ---------------------------------------------------------------------------
// k_fill: 4 edges per thread, vectorized src+dst loads, atomic-cursor scatter.
// ---------------------------------------------------------------------------
__global__ void k_fill(const void* __restrict__ ei, int e, int n, int vec_ok) {
    int b = (blockIdx.x * blockDim.x + threadIdx.x) * 4;
    if (b >= e) return;
    int sI[4], dI[4];
    if (g_is64) {
        const long long* src = (const long long*)ei;
        const long long* dst = src + e;
        if (vec_ok && b + 3 < e) {
            longlong2 s0 = __ldg((const longlong2*)(src + b));
            longlong2 s1 = __ldg((const longlong2*)(src + b + 2));
            longlong2 d0 = __ldg((const longlong2*)(dst + b));
            longlong2 d1 = __ldg((const longlong2*)(dst + b + 2));
            sI[0]=(int)s0.x; sI[1]=(int)s0.y; sI[2]=(int)s1.x; sI[3]=(int)s1.y;
            dI[0]=(int)d0.x; dI[1]=(int)d0.y; dI[2]=(int)d1.x; dI[3]=(int)d1.y;
        } else {
#pragma unroll
            for (int k = 0; k < 4; k++) {
                sI[k] = (b + k < e) ? (int)src[b + k] : -1;
                dI[k] = (b + k < e) ? (int)dst[b + k] : -1;
            }
        }
    } else {
        const int* src = (const int*)ei;
        const int* dst = src + e;
        if (vec_ok && b + 3 < e) {
            int4 sp = __ldg((const int4*)(src + b));
            int4 dp = __ldg((const int4*)(dst + b));
            sI[0]=sp.x; sI[1]=sp.y; sI[2]=sp.z; sI[3]=sp.w;
            dI[0]=dp.x; dI[1]=dp.y; dI[2]=dp.z; dI[3]=dp.w;
        } else {
#pragma unroll
            for (int k = 0; k < 4; k++) {
                sI[k] = (b + k < e) ? src[b + k] : -1;
                dI[k] = (b + k < e) ? dst[b + k] : -1;
            }
        }
    }
#pragma unroll
    for (int k = 0; k < 4; k++) {
        if (b + k < e && sI[k] >= 0 && sI[k] < n && dI[k] >= 0 && dI[k] < n) {
            int p = atomicAdd(&g_cursor[dI[k]], 1);
            g_col[p] = sI[k];
        }
    }
}

// ---------------------------------------------------------------------------
// GEMM [n,64]@[64,64] with packed f32x2 FMA (as R10).
// mode 0: out = fp16( dis[row] * (A@W) ) -> g_h16
// mode 1: out = A@W + bias               -> outf
// ---------------------------------------------------------------------------
__global__ __launch_bounds__(256) void k_gemm(const float* __restrict__ A_ext,
                                              const float* __restrict__ W,
                                              const float* __restrict__ bias,
                                              float* __restrict__ outf,
                                              int n, int mode) {
    const float* A = A_ext ? A_ext : (const float*)g_acc;

    __shared__ __align__(16) float2 Wp[32 * FD];  // [t][c] = (W[2t][c], W[2t+1][c])
    __shared__ __align__(16) float  As[FD * FD];

    int tid = threadIdx.x;
    for (int idx = tid; idx < 32 * FD; idx += 256) {
        int t = idx >> 6, c = idx & 63;
        Wp[idx] = make_float2(W[(2 * t) * FD + c], W[(2 * t + 1) * FD + c]);
    }
    int rowbase = blockIdx.x * FD;
    {
        const float4* A4 = (const float4*)(A + (size_t)rowbase * FD);
        float4* As4 = (float4*)As;
        int lim = (n - rowbase) * (FD / 4);
        for (int idx = tid; idx < FD * FD / 4; idx += 256)
            As4[idx] = (idx < lim) ? A4[idx] : make_float4(0.f, 0.f, 0.f, 0.f);
    }
    __syncthreads();

    int lane = tid & 31;
    int warp = tid >> 5;

    u64 acc0p[8], acc1p[8];
#pragma unroll
    for (int j = 0; j < 8; j++) { acc0p[j] = 0ull; acc1p[j] = 0ull; }

    const u64* As2 = (const u64*)As;
    const u64* Wp2 = (const u64*)Wp;

#pragma unroll
    for (int t = 0; t < 32; t++) {
        u64 w0 = Wp2[t * FD + lane];
        u64 w1 = Wp2[t * FD + lane + 32];
#pragma unroll
        for (int j = 0; j < 8; j++) {
            u64 aa = As2[(warp * 8 + j) * 32 + t];
            fma2(acc0p[j], aa, w0);
            fma2(acc1p[j], aa, w1);
        }
    }

    if (mode == 0) {
#pragma unroll
        for (int j = 0; j < 8; j++) {
            int r = rowbase + warp * 8 + j;
            if (r < n) {
                float d = g_dis[r];
                g_h16[r * FD + lane]      = __float2half_rn(d * hsum2(acc0p[j]));
                g_h16[r * FD + lane + 32] = __float2half_rn(d * hsum2(acc1p[j]));
            }
        }
    } else {
        float b0 = bias[lane], b1 = bias[lane + 32];
#pragma unroll
        for (int j = 0; j < 8; j++) {
            int r = rowbase + warp * 8 + j;
            if (r < n) {
                outf[r * FD + lane]      = hsum2(acc0p[j]) + b0;
                outf[r * FD + lane + 32] = hsum2(acc1p[j]) + b1;
            }
        }
    }
}

// ---------------------------------------------------------------------------
// GCN aggregation: warp per dst node; col indices read as aligned int4
// (rowstart is a multiple of 4). Full int4 groups unconditional, scalar tail.
// out[i] = relu( b + dis_i * ( h'[i] + sum h'[src] ) )
// ---------------------------------------------------------------------------
__global__ void k_aggr(const float* __restrict__ bias, int n) {
    int i = (blockIdx.x * blockDim.x + threadIdx.x) >> 5;
    int lane = threadIdx.x & 31;
    if (i >= n) return;

    const __half2* h2 = (const __half2*)g_h16;

    float2 self = __half22float2(h2[i * 32 + lane]);
    float ax = self.x, ay = self.y;

    int start = g_rowstart[i];          // multiple of 4 -> 16B aligned
    int len   = g_deg[i];
    const int4* c4 = (const int4*)(g_col + start);
    int nf = len >> 2;
#pragma unroll 2
    for (int q = 0; q < nf; q++) {
        int4 cc = __ldg(&c4[q]);
        float2 v0 = __half22float2(__ldg(&h2[cc.x * 32 + lane]));
        float2 v1 = __half22float2(__ldg(&h2[cc.y * 32 + lane]));
        float2 v2 = __half22float2(__ldg(&h2[cc.z * 32 + lane]));
        float2 v3 = __half22float2(__ldg(&h2[cc.w * 32 + lane]));
        ax += (v0.x + v1.x) + (v2.x + v3.x);
        ay += (v0.y + v1.y) + (v2.y + v3.y);
    }
    for (int j = nf * 4; j < len; j++) {
        int s = __ldg(&g_col[start + j]);
        float2 v = __half22float2(__ldg(&h2[s * 32 + lane]));
        ax += v.x;
        ay += v.y;
    }

    float di = g_dis[i];
    float bx = bias[2 * lane], by = bias[2 * lane + 1];
    ax = fmaxf(fmaf(di, ax, bx), 0.f);
    ay = fmaxf(fmaf(di, ay, by), 0.f);
    ((float2*)g_acc)[i * 32 + lane] = make_float2(ax, ay);
}

// ---------------------------------------------------------------------------
// Launch — kernel launches ONLY (graph-capture-safe)
// ---------------------------------------------------------------------------
extern "C" void kernel_launch(void* const* d_in, const int* in_sizes, int n_in,
                              void* d_out, int out_size) {
    const float* x  = (const float*)d_in[0];
    const void*  ei = d_in[1];                 // int32 or int64 — sniffed on device
    const float* W1 = (const float*)d_in[2];
    const float* b1 = (const float*)d_in[3];
    const float* W2 = (const float*)d_in[4];
    const float* b2 = (const float*)d_in[5];
    // d_in[6..9] = Wq,bq,Wk,bk : dead (softmax over length-1 axis == 1)
    const float* Wv = (const float*)d_in[10];
    const float* bv = (const float*)d_in[11];

    int n = in_sizes[0] / FD;
    int e = in_sizes[1] / 2;
    float* outp = (float*)d_out;

    int vec_ok = ((e & 3) == 0) ? 1 : 0;       // 16B-aligned vector loads valid
    int nb  = (n + 255) / 256;
    int e4  = (e + 1023) / 1024;               // 4 edges/thread, 256 thr/block
    int gemm_blocks = (n + 63) / 64;
    int aggr_blocks = (n + 7) / 8;

    k_zero_sniff<<<nb, 256>>>((const int*)ei, n);                       // 0
    k_count<<<e4, 256>>>(ei, e, n, vec_ok);                             // 1
    k_scan<<<nb, 256>>>(n);                                             // 2
    k_gemm<<<gemm_blocks, 256>>>(x, W1, nullptr, nullptr, n, 0);        // 3
    k_fill<<<e4, 256>>>(ei, e, n, vec_ok);                              // 4
    k_aggr<<<aggr_blocks, 256>>>(b1, n);                                // 5
    k_gemm<<<gemm_blocks, 256>>>(nullptr, W2, nullptr, nullptr, n, 0);  // 6
    k_aggr<<<aggr_blocks, 256>>>(b2, n);                                // 7
    k_gemm<<<gemm_blocks, 256>>>(nullptr, Wv, bv, outp, n, 1);          // 8
}

// round 14
// speedup vs baseline: 1.2372x; 1.2372x over previous
#include <cuda_runtime.h>
#include <cuda_fp16.h>

// AttGCNEncoder: 2x GCNConv(relu) + single-token attention.
// softmax over length-1 axis == 1  =>  output = relu(gcn2) @ Wv + bv.
//
// R13: tcgen05 unavailable (harness emits compute_103 PTX without 'a'
// feature). GEMMs use classic HMMA: mma.sync.m16n8k16 + ldmatrix.
//  - layers 1/2: fp16 in, f32 accum, dis folded into epilogue -> g_h16
//  - final Wv:   hi/lo fp16 split (3 mma passes) -> ~fp32 precision

#define FD 64
#define MAXN 100000
#define MAXE 3200000
#define MAXCOL (MAXE + 3 * MAXN + 16)

__device__ int    g_deg[MAXN];
__device__ int    g_rowstart[MAXN];
__device__ int    g_cursor[MAXN];
__device__ float  g_dis[MAXN];
__device__ __align__(16) int g_col[MAXCOL];
__device__ __align__(16) __half g_h16[MAXN * FD];   // dis-scaled linear out
__device__ __align__(16) __half g_a16[MAXN * FD];   // layer-1 activations
__device__ __align__(16) float  g_acc[MAXN * FD];   // layer-2 activations
__device__ unsigned long long g_bstate[1024];
__device__ int    g_is64;

typedef unsigned long long u64;
typedef unsigned int u32;

// ---------------- helpers ----------------
__device__ __forceinline__ u32 smem_u32(const void* p) {
    u32 a;
    asm("{ .reg .u64 t; cvta.to.shared.u64 t, %1; cvt.u32.u64 %0, t; }"
        : "=r"(a) : "l"(p));
    return a;
}
__device__ __forceinline__ u32 swz(u32 off) { return off ^ ((off >> 3) & 0x70); }
__device__ __forceinline__ u32 pack2(float a, float b) {
    __half2 h = __floats2half2_rn(a, b);
    return *reinterpret_cast<u32*>(&h);
}
__device__ __forceinline__ void ldmA(u32& a0, u32& a1, u32& a2, u32& a3, u32 addr) {
    asm volatile("ldmatrix.sync.aligned.m8n8.x4.shared.b16 {%0,%1,%2,%3}, [%4];"
                 : "=r"(a0), "=r"(a1), "=r"(a2), "=r"(a3) : "r"(addr));
}
__device__ __forceinline__ void ldmB(u32& b0, u32& b1, u32 addr) {
    asm volatile("ldmatrix.sync.aligned.m8n8.x2.trans.shared.b16 {%0,%1}, [%2];"
                 : "=r"(b0), "=r"(b1) : "r"(addr));
}
__device__ __forceinline__ void mma16816(float* c, u32 a0, u32 a1, u32 a2, u32 a3,
                                         u32 b0, u32 b1) {
    asm volatile(
        "mma.sync.aligned.m16n8k16.row.col.f32.f16.f16.f32 "
        "{%0,%1,%2,%3}, {%4,%5,%6,%7}, {%8,%9}, {%0,%1,%2,%3};"
        : "+f"(c[0]), "+f"(c[1]), "+f"(c[2]), "+f"(c[3])
        : "r"(a0), "r"(a1), "r"(a2), "r"(a3), "r"(b0), "r"(b1));
}

// ---------------------------------------------------------------------------
// zero deg + lookback state + dtype sniff
// ---------------------------------------------------------------------------
__global__ void k_zero_sniff(const int* __restrict__ ei32, int n) {
    int i = blockIdx.x * blockDim.x + threadIdx.x;
    if (i < n) g_deg[i] = 0;
    if (i < 1024) g_bstate[i] = 0ull;
    if (i == 0) {
        int acc = 0;
#pragma unroll
        for (int j = 0; j < 16; j++) acc |= ei32[2 * j + 1];
        g_is64 = (acc == 0) ? 1 : 0;
    }
}

// ---------------------------------------------------------------------------
// k_count / k_scan / k_fill  (as R11, proven)
// ---------------------------------------------------------------------------
__global__ void k_count(const void* __restrict__ ei, int e, int n, int vec_ok) {
    int b = (blockIdx.x * blockDim.x + threadIdx.x) * 4;
    if (b >= e) return;
    int d[4];
    if (g_is64) {
        const long long* dst = (const long long*)ei + e;
        if (vec_ok && b + 3 < e) {
            longlong2 p0 = __ldg((const longlong2*)(dst + b));
            longlong2 p1 = __ldg((const longlong2*)(dst + b + 2));
            d[0] = (int)p0.x; d[1] = (int)p0.y; d[2] = (int)p1.x; d[3] = (int)p1.y;
        } else {
#pragma unroll
            for (int k = 0; k < 4; k++) d[k] = (b + k < e) ? (int)dst[b + k] : -1;
        }
    } else {
        const int* dst = (const int*)ei + e;
        if (vec_ok && b + 3 < e) {
            int4 p = __ldg((const int4*)(dst + b));
            d[0] = p.x; d[1] = p.y; d[2] = p.z; d[3] = p.w;
        } else {
#pragma unroll
            for (int k = 0; k < 4; k++) d[k] = (b + k < e) ? dst[b + k] : -1;
        }
    }
#pragma unroll
    for (int k = 0; k < 4; k++)
        if (b + k < e && d[k] >= 0 && d[k] < n) atomicAdd(&g_deg[d[k]], 1);
}

__global__ void k_scan(int n) {
    __shared__ int s[256];
    __shared__ int s_excl;
    int t = threadIdx.x;
    int i = blockIdx.x * 256 + t;
    int deg = (i < n) ? g_deg[i] : 0;
    int v = (deg + 3) & ~3;
    s[t] = v;
    __syncthreads();
#pragma unroll
    for (int off = 1; off < 256; off <<= 1) {
        int x = (t >= off) ? s[t - off] : 0;
        __syncthreads();
        s[t] += x;
        __syncthreads();
    }
    int blocksum = s[255];
    if (t == 0) {
        int excl = 0;
        if (blockIdx.x > 0) {
            atomicExch(&g_bstate[blockIdx.x], (1ull << 32) | (unsigned)blocksum);
            for (int b = blockIdx.x - 1;;) {
                unsigned long long st;
                do { st = atomicAdd(&g_bstate[b], 0ull); } while ((st >> 32) == 0);
                excl += (int)(unsigned)st;
                if ((st >> 32) == 2) break;
                b--;
            }
        }
        atomicExch(&g_bstate[blockIdx.x], (2ull << 32) | (unsigned)(excl + blocksum));
        s_excl = excl;
    }
    __syncthreads();
    if (i < n) {
        int excl_i = s_excl + s[t] - v;
        g_rowstart[i] = excl_i;
        g_cursor[i]   = excl_i;
        g_dis[i] = rsqrtf((float)(deg + 1));
    }
}

__global__ void k_fill(const void* __restrict__ ei, int e, int n, int vec_ok) {
    int b = (blockIdx.x * blockDim.x + threadIdx.x) * 4;
    if (b >= e) return;
    int sI[4], dI[4];
    if (g_is64) {
        const long long* src = (const long long*)ei;
        const long long* dst = src + e;
        if (vec_ok && b + 3 < e) {
            longlong2 s0 = __ldg((const longlong2*)(src + b));
            longlong2 s1 = __ldg((const longlong2*)(src + b + 2));
            longlong2 d0 = __ldg((const longlong2*)(dst + b));
            longlong2 d1 = __ldg((const longlong2*)(dst + b + 2));
            sI[0]=(int)s0.x; sI[1]=(int)s0.y; sI[2]=(int)s1.x; sI[3]=(int)s1.y;
            dI[0]=(int)d0.x; dI[1]=(int)d0.y; dI[2]=(int)d1.x; dI[3]=(int)d1.y;
        } else {
#pragma unroll
            for (int k = 0; k < 4; k++) {
                sI[k] = (b + k < e) ? (int)src[b + k] : -1;
                dI[k] = (b + k < e) ? (int)dst[b + k] : -1;
            }
        }
    } else {
        const int* src = (const int*)ei;
        const int* dst = src + e;
        if (vec_ok && b + 3 < e) {
            int4 sp = __ldg((const int4*)(src + b));
            int4 dp = __ldg((const int4*)(dst + b));
            sI[0]=sp.x; sI[1]=sp.y; sI[2]=sp.z; sI[3]=sp.w;
            dI[0]=dp.x; dI[1]=dp.y; dI[2]=dp.z; dI[3]=dp.w;
        } else {
#pragma unroll
            for (int k = 0; k < 4; k++) {
                sI[k] = (b + k < e) ? src[b + k] : -1;
                dI[k] = (b + k < e) ? dst[b + k] : -1;
            }
        }
    }
#pragma unroll
    for (int k = 0; k < 4; k++) {
        if (b + k < e && sI[k] >= 0 && sI[k] < n && dI[k] >= 0 && dI[k] < n) {
            int p = atomicAdd(&g_cursor[dI[k]], 1);
            g_col[p] = sI[k];
        }
    }
}

// ---------------------------------------------------------------------------
// HMMA GEMM for layers 1/2: [n,64]@[64,64], 128 rows/CTA (8 warps x 16 rows).
// A: fp16 (asel=1 -> g_a16) or fp32-converted (asel=0 -> x).
// W: fp32 in gmem, converted to fp16 row-major [k][n] during staging.
// Epilogue: g_h16[r] = fp16( dis[r] * acc[r] ).
// SMEM tiles use the 128B XOR swizzle for conflict-free ldmatrix.
// ---------------------------------------------------------------------------
__global__ __launch_bounds__(256) void k_hgemm(const float* __restrict__ Af32,
                                               const float* __restrict__ W,
                                               int asel, int n) {
    __shared__ __align__(1024) __half sA[128 * FD];   // 16KB
    __shared__ __align__(1024) __half sB[FD * FD];    // 8KB

    int tid = threadIdx.x;
    int rowbase = blockIdx.x * 128;
    char* sAb = (char*)sA;
    char* sBb = (char*)sB;

    // Stage A (128 rows x 8 chunks of 16B), swizzled
#pragma unroll
    for (int it = 0; it < 4; it++) {
        int idx = tid + it * 256;            // 0..1023
        int r = idx >> 3, c = idx & 7;
        int gr = rowbase + r;
        uint4 v;
        if (gr < n) {
            if (asel) {
                v = __ldg((const uint4*)(g_a16 + (size_t)gr * FD + c * 8));
            } else {
                const float4* s = (const float4*)(Af32 + (size_t)gr * FD + c * 8);
                float4 f0 = __ldg(s), f1 = __ldg(s + 1);
                v.x = pack2(f0.x, f0.y); v.y = pack2(f0.z, f0.w);
                v.z = pack2(f1.x, f1.y); v.w = pack2(f1.z, f1.w);
            }
        } else v = make_uint4(0, 0, 0, 0);
        *(uint4*)(sAb + swz((u32)(r * 128 + c * 16))) = v;
    }
    // Stage B = fp16(W) row-major [k][n], swizzled
#pragma unroll
    for (int it = 0; it < 2; it++) {
        int idx = tid + it * 256;            // 0..511
        int k = idx >> 3, c = idx & 7;
        const float4* s = (const float4*)(W + (size_t)k * FD + c * 8);
        float4 f0 = __ldg(s), f1 = __ldg(s + 1);
        uint4 v;
        v.x = pack2(f0.x, f0.y); v.y = pack2(f0.z, f0.w);
        v.z = pack2(f1.x, f1.y); v.w = pack2(f1.z, f1.w);
        *(uint4*)(sBb + swz((u32)(k * 128 + c * 16))) = v;
    }
    __syncthreads();

    int lane = tid & 31;
    int warp = tid >> 5;
    u32 baseA = smem_u32(sA);
    u32 baseB = smem_u32(sB);

    // A fragments for 4 k-steps
    u32 a[4][4];
    {
        int r = warp * 16 + (lane & 15);
        int cbyte = (lane >> 4) * 16;
#pragma unroll
        for (int k = 0; k < 4; k++)
            ldmA(a[k][0], a[k][1], a[k][2], a[k][3],
                 baseA + swz((u32)(r * 128 + cbyte + k * 32)));
    }

    float c[8][4];
#pragma unroll
    for (int nt = 0; nt < 8; nt++)
#pragma unroll
        for (int j = 0; j < 4; j++) c[nt][j] = 0.f;

#pragma unroll
    for (int k = 0; k < 4; k++) {
        int br = k * 16 + (lane & 15);
#pragma unroll
        for (int nt = 0; nt < 8; nt++) {
            u32 b0, b1;
            ldmB(b0, b1, baseB + swz((u32)(br * 128 + nt * 16)));
            mma16816(c[nt], a[k][0], a[k][1], a[k][2], a[k][3], b0, b1);
        }
    }

    // Epilogue: scale by dis, store fp16
    int gr0 = rowbase + warp * 16 + (lane >> 2);
    int gr1 = gr0 + 8;
    float d0 = (gr0 < n) ? g_dis[gr0] : 0.f;
    float d1 = (gr1 < n) ? g_dis[gr1] : 0.f;
#pragma unroll
    for (int nt = 0; nt < 8; nt++) {
        int col = nt * 8 + (lane & 3) * 2;
        if (gr0 < n)
            *(__half2*)(g_h16 + (size_t)gr0 * FD + col) =
                __floats2half2_rn(d0 * c[nt][0], d0 * c[nt][1]);
        if (gr1 < n)
            *(__half2*)(g_h16 + (size_t)gr1 * FD + col) =
                __floats2half2_rn(d1 * c[nt][2], d1 * c[nt][3]);
    }
}

// ---------------------------------------------------------------------------
// Final Wv GEMM with hi/lo fp16 split: D = Ah@Wh + Al@Wh + Ah@Wl  (+ bias)
// 64 rows/CTA, 128 threads (4 warps x 16 rows). fp32 output to d_out.
// ---------------------------------------------------------------------------
__global__ __launch_bounds__(128) void k_hgemm_split(const float* __restrict__ W,
                                                     const float* __restrict__ bias,
                                                     float* __restrict__ outf, int n) {
    __shared__ __align__(1024) __half sAh[64 * FD];   // 8KB
    __shared__ __align__(1024) __half sAl[64 * FD];   // 8KB
    __shared__ __align__(1024) __half sBh[FD * FD];   // 8KB
    __shared__ __align__(1024) __half sBl[FD * FD];   // 8KB

    int tid = threadIdx.x;
    int rowbase = blockIdx.x * 64;
    char *sAhb = (char*)sAh, *sAlb = (char*)sAl;
    char *sBhb = (char*)sBh, *sBlb = (char*)sBl;

    // Stage A hi/lo (64 rows x 8 chunks)
#pragma unroll
    for (int it = 0; it < 4; it++) {
        int idx = tid + it * 128;            // 0..511
        int r = idx >> 3, c = idx & 7;
        int gr = rowbase + r;
        uint4 vh = make_uint4(0,0,0,0), vl = make_uint4(0,0,0,0);
        if (gr < n) {
            const float4* s = (const float4*)(g_acc + (size_t)gr * FD + c * 8);
            float4 f0 = __ldg(s), f1 = __ldg(s + 1);
            float f[8] = {f0.x,f0.y,f0.z,f0.w,f1.x,f1.y,f1.z,f1.w};
            u32 ph[4], pl[4];
#pragma unroll
            for (int q = 0; q < 4; q++) {
                __half h0 = __float2half_rn(f[2*q]);
                __half h1 = __float2half_rn(f[2*q+1]);
                __half l0 = __float2half_rn(f[2*q]   - __half2float(h0));
                __half l1 = __float2half_rn(f[2*q+1] - __half2float(h1));
                __half2 hh = __halves2half2(h0, h1);
                __half2 ll = __halves2half2(l0, l1);
                ph[q] = *reinterpret_cast<u32*>(&hh);
                pl[q] = *reinterpret_cast<u32*>(&ll);
            }
            vh = make_uint4(ph[0], ph[1], ph[2], ph[3]);
            vl = make_uint4(pl[0], pl[1], pl[2], pl[3]);
        }
        u32 off = swz((u32)(r * 128 + c * 16));
        *(uint4*)(sAhb + off) = vh;
        *(uint4*)(sAlb + off) = vl;
    }
    // Stage B hi/lo
#pragma unroll
    for (int it = 0; it < 4; it++) {
        int idx = tid + it * 128;            // 0..511
        int k = idx >> 3, c = idx & 7;
        const float4* s = (const float4*)(W + (size_t)k * FD + c * 8);
        float4 f0 = __ldg(s), f1 = __ldg(s + 1);
        float f[8] = {f0.x,f0.y,f0.z,f0.w,f1.x,f1.y,f1.z,f1.w};
        u32 ph[4], pl[4];
#pragma unroll
        for (int q = 0; q < 4; q++) {
            __half h0 = __float2half_rn(f[2*q]);
            __half h1 = __float2half_rn(f[2*q+1]);
            __half l0 = __float2half_rn(f[2*q]   - __half2float(h0));
            __half l1 = __float2half_rn(f[2*q+1] - __half2float(h1));
            __half2 hh = __halves2half2(h0, h1);
            __half2 ll = __halves2half2(l0, l1);
            ph[q] = *reinterpret_cast<u32*>(&hh);
            pl[q] = *reinterpret_cast<u32*>(&ll);
        }
        u32 off = swz((u32)(k * 128 + c * 16));
        *(uint4*)(sBhb + off) = make_uint4(ph[0], ph[1], ph[2], ph[3]);
        *(uint4*)(sBlb + off) = make_uint4(pl[0], pl[1], pl[2], pl[3]);
    }
    __syncthreads();

    int lane = tid & 31;
    int warp = tid >> 5;
    u32 bAh = smem_u32(sAh), bAl = smem_u32(sAl);
    u32 bBh = smem_u32(sBh), bBl = smem_u32(sBl);

    u32 ah[4][4], al[4][4];
    {
        int r = warp * 16 + (lane & 15);
        int cbyte = (lane >> 4) * 16;
#pragma unroll
        for (int k = 0; k < 4; k++) {
            u32 off = swz((u32)(r * 128 + cbyte + k * 32));
            ldmA(ah[k][0], ah[k][1], ah[k][2], ah[k][3], bAh + off);
            ldmA(al[k][0], al[k][1], al[k][2], al[k][3], bAl + off);
        }
    }

    float c[8][4];
#pragma unroll
    for (int nt = 0; nt < 8; nt++)
#pragma unroll
        for (int j = 0; j < 4; j++) c[nt][j] = 0.f;

#pragma unroll
    for (int k = 0; k < 4; k++) {
        int br = k * 16 + (lane & 15);
#pragma unroll
        for (int nt = 0; nt < 8; nt++) {
            u32 off = swz((u32)(br * 128 + nt * 16));
            u32 bh0, bh1, bl0, bl1;
            ldmB(bh0, bh1, bBh + off);
            ldmB(bl0, bl1, bBl + off);
            mma16816(c[nt], ah[k][0], ah[k][1], ah[k][2], ah[k][3], bh0, bh1);
            mma16816(c[nt], al[k][0], al[k][1], al[k][2], al[k][3], bh0, bh1);
            mma16816(c[nt], ah[k][0], ah[k][1], ah[k][2], ah[k][3], bl0, bl1);
        }
    }

    int gr0 = rowbase + warp * 16 + (lane >> 2);
    int gr1 = gr0 + 8;
#pragma unroll
    for (int nt = 0; nt < 8; nt++) {
        int col = nt * 8 + (lane & 3) * 2;
        float bx = bias[col], by = bias[col + 1];
        if (gr0 < n)
            *(float2*)(outf + (size_t)gr0 * FD + col) =
                make_float2(c[nt][0] + bx, c[nt][1] + by);
        if (gr1 < n)
            *(float2*)(outf + (size_t)gr1 * FD + col) =
                make_float2(c[nt][2] + bx, c[nt][3] + by);
    }
}

// ---------------------------------------------------------------------------
// GCN aggregation: warp per dst node; aligned-int4 col reads.
// mode 0 -> write fp16 g_a16 ; mode 1 -> write fp32 g_acc
// ---------------------------------------------------------------------------
__global__ void k_aggr(const float* __restrict__ bias, int n, int mode) {
    int i = (blockIdx.x * blockDim.x + threadIdx.x) >> 5;
    int lane = threadIdx.x & 31;
    if (i >= n) return;

    const __half2* h2 = (const __half2*)g_h16;
    float2 self = __half22float2(h2[i * 32 + lane]);
    float ax = self.x, ay = self.y;

    int start = g_rowstart[i];
    int len   = g_deg[i];
    const int4* c4 = (const int4*)(g_col + start);
    int nf = len >> 2;
#pragma unroll 2
    for (int q = 0; q < nf; q++) {
        int4 cc = __ldg(&c4[q]);
        float2 v0 = __half22float2(__ldg(&h2[cc.x * 32 + lane]));
        float2 v1 = __half22float2(__ldg(&h2[cc.y * 32 + lane]));
        float2 v2 = __half22float2(__ldg(&h2[cc.z * 32 + lane]));
        float2 v3 = __half22float2(__ldg(&h2[cc.w * 32 + lane]));
        ax += (v0.x + v1.x) + (v2.x + v3.x);
        ay += (v0.y + v1.y) + (v2.y + v3.y);
    }
    for (int j = nf * 4; j < len; j++) {
        int s = __ldg(&g_col[start + j]);
        float2 v = __half22float2(__ldg(&h2[s * 32 + lane]));
        ax += v.x;
        ay += v.y;
    }

    float di = g_dis[i];
    float bx = bias[2 * lane], by = bias[2 * lane + 1];
    ax = fmaxf(fmaf(di, ax, bx), 0.f);
    ay = fmaxf(fmaf(di, ay, by), 0.f);
    if (mode == 0)
        ((__half2*)g_a16)[i * 32 + lane] = __floats2half2_rn(ax, ay);
    else
        ((float2*)g_acc)[i * 32 + lane] = make_float2(ax, ay);
}

// ---------------------------------------------------------------------------
// Launch — kernel launches ONLY (graph-capture-safe)
// ---------------------------------------------------------------------------
extern "C" void kernel_launch(void* const* d_in, const int* in_sizes, int n_in,
                              void* d_out, int out_size) {
    const float* x  = (const float*)d_in[0];
    const void*  ei = d_in[1];
    const float* W1 = (const float*)d_in[2];
    const float* b1 = (const float*)d_in[3];
    const float* W2 = (const float*)d_in[4];
    const float* b2 = (const float*)d_in[5];
    // d_in[6..9] = Wq,bq,Wk,bk : dead (softmax over length-1 axis == 1)
    const float* Wv = (const float*)d_in[10];
    const float* bv = (const float*)d_in[11];

    int n = in_sizes[0] / FD;
    int e = in_sizes[1] / 2;
    float* outp = (float*)d_out;

    int vec_ok = ((e & 3) == 0) ? 1 : 0;
    int nb  = (n + 255) / 256;
    int e4  = (e + 1023) / 1024;
    int hg_blocks = (n + 127) / 128;
    int sp_blocks = (n + 63) / 64;
    int aggr_blocks = (n + 7) / 8;

    k_zero_sniff<<<nb, 256>>>((const int*)ei, n);              // 0
    k_count<<<e4, 256>>>(ei, e, n, vec_ok);                    // 1
    k_scan<<<nb, 256>>>(n);                                    // 2
    k_hgemm<<<hg_blocks, 256>>>(x, W1, 0, n);                  // 3
    k_fill<<<e4, 256>>>(ei, e, n, vec_ok);                     // 4
    k_aggr<<<aggr_blocks, 256>>>(b1, n, 0);                    // 5  (ncu)
    k_hgemm<<<hg_blocks, 256>>>(nullptr, W2, 1, n);            // 6
    k_aggr<<<aggr_blocks, 256>>>(b2, n, 1);                    // 7
    k_hgemm_split<<<sp_blocks, 128>>>(Wv, bv, outp, n);        // 8
}

// round 15
// speedup vs baseline: 1.2666x; 1.0237x over previous
#include <cuda_runtime.h>
#include <cuda_fp16.h>

// AttGCNEncoder: 2x GCNConv(relu) + single-token attention.
// softmax over length-1 axis == 1  =>  output = relu(gcn2) @ Wv + bv.
//
// R15 vs R14 (205.6us): gemm1 and fill are independent (both depend only on
// scan) but were serialized on one stream. Merged into one block-partitioned
// kernel -> gemm1's 15us hides under fill's ~35us; one fewer launch.
// GEMMs: mma.sync.m16n8k16 HMMA (tcgen05 PTX not accepted by this toolchain).

#define FD 64
#define MAXN 100000
#define MAXE 3200000
#define MAXCOL (MAXE + 3 * MAXN + 16)

__device__ int    g_deg[MAXN];
__device__ int    g_rowstart[MAXN];
__device__ int    g_cursor[MAXN];
__device__ float  g_dis[MAXN];
__device__ __align__(16) int g_col[MAXCOL];
__device__ __align__(16) __half g_h16[MAXN * FD];   // dis-scaled linear out
__device__ __align__(16) __half g_a16[MAXN * FD];   // layer-1 activations
__device__ __align__(16) float  g_acc[MAXN * FD];   // layer-2 activations
__device__ unsigned long long g_bstate[1024];
__device__ int    g_is64;

typedef unsigned long long u64;
typedef unsigned int u32;

// ---------------- helpers ----------------
__device__ __forceinline__ u32 smem_u32(const void* p) {
    u32 a;
    asm("{ .reg .u64 t; cvta.to.shared.u64 t, %1; cvt.u32.u64 %0, t; }"
        : "=r"(a) : "l"(p));
    return a;
}
__device__ __forceinline__ u32 swz(u32 off) { return off ^ ((off >> 3) & 0x70); }
__device__ __forceinline__ u32 pack2(float a, float b) {
    __half2 h = __floats2half2_rn(a, b);
    return *reinterpret_cast<u32*>(&h);
}
__device__ __forceinline__ void ldmA(u32& a0, u32& a1, u32& a2, u32& a3, u32 addr) {
    asm volatile("ldmatrix.sync.aligned.m8n8.x4.shared.b16 {%0,%1,%2,%3}, [%4];"
                 : "=r"(a0), "=r"(a1), "=r"(a2), "=r"(a3) : "r"(addr));
}
__device__ __forceinline__ void ldmB(u32& b0, u32& b1, u32 addr) {
    asm volatile("ldmatrix.sync.aligned.m8n8.x2.trans.shared.b16 {%0,%1}, [%2];"
                 : "=r"(b0), "=r"(b1) : "r"(addr));
}
__device__ __forceinline__ void mma16816(float* c, u32 a0, u32 a1, u32 a2, u32 a3,
                                         u32 b0, u32 b1) {
    asm volatile(
        "mma.sync.aligned.m16n8k16.row.col.f32.f16.f16.f32 "
        "{%0,%1,%2,%3}, {%4,%5,%6,%7}, {%8,%9}, {%0,%1,%2,%3};"
        : "+f"(c[0]), "+f"(c[1]), "+f"(c[2]), "+f"(c[3])
        : "r"(a0), "r"(a1), "r"(a2), "r"(a3), "r"(b0), "r"(b1));
}

// ---------------------------------------------------------------------------
// zero deg + lookback state + dtype sniff
// ---------------------------------------------------------------------------
__global__ void k_zero_sniff(const int* __restrict__ ei32, int n) {
    int i = blockIdx.x * blockDim.x + threadIdx.x;
    if (i < n) g_deg[i] = 0;
    if (i < 1024) g_bstate[i] = 0ull;
    if (i == 0) {
        int acc = 0;
#pragma unroll
        for (int j = 0; j < 16; j++) acc |= ei32[2 * j + 1];
        g_is64 = (acc == 0) ? 1 : 0;
    }
}

// ---------------------------------------------------------------------------
// k_count / k_scan  (proven)
// ---------------------------------------------------------------------------
__global__ void k_count(const void* __restrict__ ei, int e, int n, int vec_ok) {
    int b = (blockIdx.x * blockDim.x + threadIdx.x) * 4;
    if (b >= e) return;
    int d[4];
    if (g_is64) {
        const long long* dst = (const long long*)ei + e;
        if (vec_ok && b + 3 < e) {
            longlong2 p0 = __ldg((const longlong2*)(dst + b));
            longlong2 p1 = __ldg((const longlong2*)(dst + b + 2));
            d[0] = (int)p0.x; d[1] = (int)p0.y; d[2] = (int)p1.x; d[3] = (int)p1.y;
        } else {
#pragma unroll
            for (int k = 0; k < 4; k++) d[k] = (b + k < e) ? (int)dst[b + k] : -1;
        }
    } else {
        const int* dst = (const int*)ei + e;
        if (vec_ok && b + 3 < e) {
            int4 p = __ldg((const int4*)(dst + b));
            d[0] = p.x; d[1] = p.y; d[2] = p.z; d[3] = p.w;
        } else {
#pragma unroll
            for (int k = 0; k < 4; k++) d[k] = (b + k < e) ? dst[b + k] : -1;
        }
    }
#pragma unroll
    for (int k = 0; k < 4; k++)
        if (b + k < e && d[k] >= 0 && d[k] < n) atomicAdd(&g_deg[d[k]], 1);
}

__global__ void k_scan(int n) {
    __shared__ int s[256];
    __shared__ int s_excl;
    int t = threadIdx.x;
    int i = blockIdx.x * 256 + t;
    int deg = (i < n) ? g_deg[i] : 0;
    int v = (deg + 3) & ~3;
    s[t] = v;
    __syncthreads();
#pragma unroll
    for (int off = 1; off < 256; off <<= 1) {
        int x = (t >= off) ? s[t - off] : 0;
        __syncthreads();
        s[t] += x;
        __syncthreads();
    }
    int blocksum = s[255];
    if (t == 0) {
        int excl = 0;
        if (blockIdx.x > 0) {
            atomicExch(&g_bstate[blockIdx.x], (1ull << 32) | (unsigned)blocksum);
            for (int b = blockIdx.x - 1;;) {
                unsigned long long st;
                do { st = atomicAdd(&g_bstate[b], 0ull); } while ((st >> 32) == 0);
                excl += (int)(unsigned)st;
                if ((st >> 32) == 2) break;
                b--;
            }
        }
        atomicExch(&g_bstate[blockIdx.x], (2ull << 32) | (unsigned)(excl + blocksum));
        s_excl = excl;
    }
    __syncthreads();
    if (i < n) {
        int excl_i = s_excl + s[t] - v;
        g_rowstart[i] = excl_i;
        g_cursor[i]   = excl_i;
        g_dis[i] = rsqrtf((float)(deg + 1));
    }
}

// ---------------------------------------------------------------------------
// fill body (device fn): 4 edges/thread, atomic-cursor scatter
// ---------------------------------------------------------------------------
__device__ __forceinline__ void fill_body(const void* __restrict__ ei, int e,
                                          int n, int vec_ok, int bid, int tid) {
    int b = (bid * 256 + tid) * 4;
    if (b >= e) return;
    int sI[4], dI[4];
    if (g_is64) {
        const long long* src = (const long long*)ei;
        const long long* dst = src + e;
        if (vec_ok && b + 3 < e) {
            longlong2 s0 = __ldg((const longlong2*)(src + b));
            longlong2 s1 = __ldg((const longlong2*)(src + b + 2));
            longlong2 d0 = __ldg((const longlong2*)(dst + b));
            longlong2 d1 = __ldg((const longlong2*)(dst + b + 2));
            sI[0]=(int)s0.x; sI[1]=(int)s0.y; sI[2]=(int)s1.x; sI[3]=(int)s1.y;
            dI[0]=(int)d0.x; dI[1]=(int)d0.y; dI[2]=(int)d1.x; dI[3]=(int)d1.y;
        } else {
#pragma unroll
            for (int k = 0; k < 4; k++) {
                sI[k] = (b + k < e) ? (int)src[b + k] : -1;
                dI[k] = (b + k < e) ? (int)dst[b + k] : -1;
            }
        }
    } else {
        const int* src = (const int*)ei;
        const int* dst = src + e;
        if (vec_ok && b + 3 < e) {
            int4 sp = __ldg((const int4*)(src + b));
            int4 dp = __ldg((const int4*)(dst + b));
            sI[0]=sp.x; sI[1]=sp.y; sI[2]=sp.z; sI[3]=sp.w;
            dI[0]=dp.x; dI[1]=dp.y; dI[2]=dp.z; dI[3]=dp.w;
        } else {
#pragma unroll
            for (int k = 0; k < 4; k++) {
                sI[k] = (b + k < e) ? src[b + k] : -1;
                dI[k] = (b + k < e) ? dst[b + k] : -1;
            }
        }
    }
#pragma unroll
    for (int k = 0; k < 4; k++) {
        if (b + k < e && sI[k] >= 0 && sI[k] < n && dI[k] >= 0 && dI[k] < n) {
            int p = atomicAdd(&g_cursor[dI[k]], 1);
            g_col[p] = sI[k];
        }
    }
}

// ---------------------------------------------------------------------------
// HMMA gemm body (device fn): 128 rows/tile, fp16 in, f32 accum,
// epilogue g_h16[r] = fp16(dis[r] * acc).
// ---------------------------------------------------------------------------
__device__ __forceinline__ void hgemm_body(const float* __restrict__ Af32,
                                           const float* __restrict__ W,
                                           int asel, int n, int rowbase,
                                           __half* sA, __half* sB, int tid) {
    char* sAb = (char*)sA;
    char* sBb = (char*)sB;

    // Stage A (128 rows x 8 chunks of 16B), swizzled
#pragma unroll
    for (int it = 0; it < 4; it++) {
        int idx = tid + it * 256;
        int r = idx >> 3, c = idx & 7;
        int gr = rowbase + r;
        uint4 v;
        if (gr < n) {
            if (asel) {
                v = __ldg((const uint4*)(g_a16 + (size_t)gr * FD + c * 8));
            } else {
                const float4* s = (const float4*)(Af32 + (size_t)gr * FD + c * 8);
                float4 f0 = __ldg(s), f1 = __ldg(s + 1);
                v.x = pack2(f0.x, f0.y); v.y = pack2(f0.z, f0.w);
                v.z = pack2(f1.x, f1.y); v.w = pack2(f1.z, f1.w);
            }
        } else v = make_uint4(0, 0, 0, 0);
        *(uint4*)(sAb + swz((u32)(r * 128 + c * 16))) = v;
    }
    // Stage B = fp16(W) row-major [k][n], swizzled
#pragma unroll
    for (int it = 0; it < 2; it++) {
        int idx = tid + it * 256;
        int k = idx >> 3, c = idx & 7;
        const float4* s = (const float4*)(W + (size_t)k * FD + c * 8);
        float4 f0 = __ldg(s), f1 = __ldg(s + 1);
        uint4 v;
        v.x = pack2(f0.x, f0.y); v.y = pack2(f0.z, f0.w);
        v.z = pack2(f1.x, f1.y); v.w = pack2(f1.z, f1.w);
        *(uint4*)(sBb + swz((u32)(k * 128 + c * 16))) = v;
    }
    __syncthreads();

    int lane = tid & 31;
    int warp = tid >> 5;
    u32 baseA = smem_u32(sA);
    u32 baseB = smem_u32(sB);

    u32 a[4][4];
    {
        int r = warp * 16 + (lane & 15);
        int cbyte = (lane >> 4) * 16;
#pragma unroll
        for (int k = 0; k < 4; k++)
            ldmA(a[k][0], a[k][1], a[k][2], a[k][3],
                 baseA + swz((u32)(r * 128 + cbyte + k * 32)));
    }

    float c[8][4];
#pragma unroll
    for (int nt = 0; nt < 8; nt++)
#pragma unroll
        for (int j = 0; j < 4; j++) c[nt][j] = 0.f;

#pragma unroll
    for (int k = 0; k < 4; k++) {
        int br = k * 16 + (lane & 15);
#pragma unroll
        for (int nt = 0; nt < 8; nt++) {
            u32 b0, b1;
            ldmB(b0, b1, baseB + swz((u32)(br * 128 + nt * 16)));
            mma16816(c[nt], a[k][0], a[k][1], a[k][2], a[k][3], b0, b1);
        }
    }

    int gr0 = rowbase + warp * 16 + (lane >> 2);
    int gr1 = gr0 + 8;
    float d0 = (gr0 < n) ? g_dis[gr0] : 0.f;
    float d1 = (gr1 < n) ? g_dis[gr1] : 0.f;
#pragma unroll
    for (int nt = 0; nt < 8; nt++) {
        int col = nt * 8 + (lane & 3) * 2;
        if (gr0 < n)
            *(__half2*)(g_h16 + (size_t)gr0 * FD + col) =
                __floats2half2_rn(d0 * c[nt][0], d0 * c[nt][1]);
        if (gr1 < n)
            *(__half2*)(g_h16 + (size_t)gr1 * FD + col) =
                __floats2half2_rn(d1 * c[nt][2], d1 * c[nt][3]);
    }
}

// ---------------------------------------------------------------------------
// Merged kernel: blocks [0, gb) run gemm1 (x @ W1, dis-scaled -> g_h16);
// blocks [gb, gb+eb) run fill. Both depend only on k_scan.
// ---------------------------------------------------------------------------
__global__ __launch_bounds__(256) void k_gemm1_fill(const float* __restrict__ x,
                                                    const float* __restrict__ W1,
                                                    const void* __restrict__ ei,
                                                    int e, int n, int vec_ok,
                                                    int gb) {
    __shared__ __align__(1024) __half sA[128 * FD];   // 16KB
    __shared__ __align__(1024) __half sB[FD * FD];    // 8KB
    if ((int)blockIdx.x < gb) {
        hgemm_body(x, W1, 0, n, blockIdx.x * 128, sA, sB, threadIdx.x);
    } else {
        fill_body(ei, e, n, vec_ok, blockIdx.x - gb, threadIdx.x);
    }
}

// Standalone layer-2 GEMM (reads g_a16)
__global__ __launch_bounds__(256) void k_hgemm2(const float* __restrict__ W, int n) {
    __shared__ __align__(1024) __half sA[128 * FD];
    __shared__ __align__(1024) __half sB[FD * FD];
    hgemm_body(nullptr, W, 1, n, blockIdx.x * 128, sA, sB, threadIdx.x);
}

// ---------------------------------------------------------------------------
// Final Wv GEMM with hi/lo fp16 split: D = Ah@Wh + Al@Wh + Ah@Wl (+bias)
// ---------------------------------------------------------------------------
__global__ __launch_bounds__(128) void k_hgemm_split(const float* __restrict__ W,
                                                     const float* __restrict__ bias,
                                                     float* __restrict__ outf, int n) {
    __shared__ __align__(1024) __half sAh[64 * FD];
    __shared__ __align__(1024) __half sAl[64 * FD];
    __shared__ __align__(1024) __half sBh[FD * FD];
    __shared__ __align__(1024) __half sBl[FD * FD];

    int tid = threadIdx.x;
    int rowbase = blockIdx.x * 64;
    char *sAhb = (char*)sAh, *sAlb = (char*)sAl;
    char *sBhb = (char*)sBh, *sBlb = (char*)sBl;

#pragma unroll
    for (int it = 0; it < 4; it++) {
        int idx = tid + it * 128;
        int r = idx >> 3, c = idx & 7;
        int gr = rowbase + r;
        uint4 vh = make_uint4(0,0,0,0), vl = make_uint4(0,0,0,0);
        if (gr < n) {
            const float4* s = (const float4*)(g_acc + (size_t)gr * FD + c * 8);
            float4 f0 = __ldg(s), f1 = __ldg(s + 1);
            float f[8] = {f0.x,f0.y,f0.z,f0.w,f1.x,f1.y,f1.z,f1.w};
            u32 ph[4], pl[4];
#pragma unroll
            for (int q = 0; q < 4; q++) {
                __half h0 = __float2half_rn(f[2*q]);
                __half h1 = __float2half_rn(f[2*q+1]);
                __half l0 = __float2half_rn(f[2*q]   - __half2float(h0));
                __half l1 = __float2half_rn(f[2*q+1] - __half2float(h1));
                __half2 hh = __halves2half2(h0, h1);
                __half2 ll = __halves2half2(l0, l1);
                ph[q] = *reinterpret_cast<u32*>(&hh);
                pl[q] = *reinterpret_cast<u32*>(&ll);
            }
            vh = make_uint4(ph[0], ph[1], ph[2], ph[3]);
            vl = make_uint4(pl[0], pl[1], pl[2], pl[3]);
        }
        u32 off = swz((u32)(r * 128 + c * 16));
        *(uint4*)(sAhb + off) = vh;
        *(uint4*)(sAlb + off) = vl;
    }
#pragma unroll
    for (int it = 0; it < 4; it++) {
        int idx = tid + it * 128;
        int k = idx >> 3, c = idx & 7;
        const float4* s = (const float4*)(W + (size_t)k * FD + c * 8);
        float4 f0 = __ldg(s), f1 = __ldg(s + 1);
        float f[8] = {f0.x,f0.y,f0.z,f0.w,f1.x,f1.y,f1.z,f1.w};
        u32 ph[4], pl[4];
#pragma unroll
        for (int q = 0; q < 4; q++) {
            __half h0 = __float2half_rn(f[2*q]);
            __half h1 = __float2half_rn(f[2*q+1]);
            __half l0 = __float2half_rn(f[2*q]   - __half2float(h0));
            __half l1 = __float2half_rn(f[2*q+1] - __half2float(h1));
            __half2 hh = __halves2half2(h0, h1);
            __half2 ll = __halves2half2(l0, l1);
            ph[q] = *reinterpret_cast<u32*>(&hh);
            pl[q] = *reinterpret_cast<u32*>(&ll);
        }
        u32 off = swz((u32)(k * 128 + c * 16));
        *(uint4*)(sBhb + off) = make_uint4(ph[0], ph[1], ph[2], ph[3]);
        *(uint4*)(sBlb + off) = make_uint4(pl[0], pl[1], pl[2], pl[3]);
    }
    __syncthreads();

    int lane = tid & 31;
    int warp = tid >> 5;
    u32 bAh = smem_u32(sAh), bAl = smem_u32(sAl);
    u32 bBh = smem_u32(sBh), bBl = smem_u32(sBl);

    u32 ah[4][4], al[4][4];
    {
        int r = warp * 16 + (lane & 15);
        int cbyte = (lane >> 4) * 16;
#pragma unroll
        for (int k = 0; k < 4; k++) {
            u32 off = swz((u32)(r * 128 + cbyte + k * 32));
            ldmA(ah[k][0], ah[k][1], ah[k][2], ah[k][3], bAh + off);
            ldmA(al[k][0], al[k][1], al[k][2], al[k][3], bAl + off);
        }
    }

    float c[8][4];
#pragma unroll
    for (int nt = 0; nt < 8; nt++)
#pragma unroll
        for (int j = 0; j < 4; j++) c[nt][j] = 0.f;

#pragma unroll
    for (int k = 0; k < 4; k++) {
        int br = k * 16 + (lane & 15);
#pragma unroll
        for (int nt = 0; nt < 8; nt++) {
            u32 off = swz((u32)(br * 128 + nt * 16));
            u32 bh0, bh1, bl0, bl1;
            ldmB(bh0, bh1, bBh + off);
            ldmB(bl0, bl1, bBl + off);
            mma16816(c[nt], ah[k][0], ah[k][1], ah[k][2], ah[k][3], bh0, bh1);
            mma16816(c[nt], al[k][0], al[k][1], al[k][2], al[k][3], bh0, bh1);
            mma16816(c[nt], ah[k][0], ah[k][1], ah[k][2], ah[k][3], bl0, bl1);
        }
    }

    int gr0 = rowbase + warp * 16 + (lane >> 2);
    int gr1 = gr0 + 8;
#pragma unroll
    for (int nt = 0; nt < 8; nt++) {
        int col = nt * 8 + (lane & 3) * 2;
        float bx = bias[col], by = bias[col + 1];
        if (gr0 < n)
            *(float2*)(outf + (size_t)gr0 * FD + col) =
                make_float2(c[nt][0] + bx, c[nt][1] + by);
        if (gr1 < n)
            *(float2*)(outf + (size_t)gr1 * FD + col) =
                make_float2(c[nt][2] + bx, c[nt][3] + by);
    }
}

// ---------------------------------------------------------------------------
// GCN aggregation: warp per dst node; aligned-int4 col reads.
// mode 0 -> write fp16 g_a16 ; mode 1 -> write fp32 g_acc
// ---------------------------------------------------------------------------
__global__ void k_aggr(const float* __restrict__ bias, int n, int mode) {
    int i = (blockIdx.x * blockDim.x + threadIdx.x) >> 5;
    int lane = threadIdx.x & 31;
    if (i >= n) return;

    const __half2* h2 = (const __half2*)g_h16;
    float2 self = __half22float2(h2[i * 32 + lane]);
    float ax = self.x, ay = self.y;

    int start = g_rowstart[i];
    int len   = g_deg[i];
    const int4* c4 = (const int4*)(g_col + start);
    int nf = len >> 2;
#pragma unroll 2
    for (int q = 0; q < nf; q++) {
        int4 cc = __ldg(&c4[q]);
        float2 v0 = __half22float2(__ldg(&h2[cc.x * 32 + lane]));
        float2 v1 = __half22float2(__ldg(&h2[cc.y * 32 + lane]));
        float2 v2 = __half22float2(__ldg(&h2[cc.z * 32 + lane]));
        float2 v3 = __half22float2(__ldg(&h2[cc.w * 32 + lane]));
        ax += (v0.x + v1.x) + (v2.x + v3.x);
        ay += (v0.y + v1.y) + (v2.y + v3.y);
    }
    for (int j = nf * 4; j < len; j++) {
        int s = __ldg(&g_col[start + j]);
        float2 v = __half22float2(__ldg(&h2[s * 32 + lane]));
        ax += v.x;
        ay += v.y;
    }

    float di = g_dis[i];
    float bx = bias[2 * lane], by = bias[2 * lane + 1];
    ax = fmaxf(fmaf(di, ax, bx), 0.f);
    ay = fmaxf(fmaf(di, ay, by), 0.f);
    if (mode == 0)
        ((__half2*)g_a16)[i * 32 + lane] = __floats2half2_rn(ax, ay);
    else
        ((float2*)g_acc)[i * 32 + lane] = make_float2(ax, ay);
}

// ---------------------------------------------------------------------------
// Launch — kernel launches ONLY (graph-capture-safe)
// ---------------------------------------------------------------------------
extern "C" void kernel_launch(void* const* d_in, const int* in_sizes, int n_in,
                              void* d_out, int out_size) {
    const float* x  = (const float*)d_in[0];
    const void*  ei = d_in[1];
    const float* W1 = (const float*)d_in[2];
    const float* b1 = (const float*)d_in[3];
    const float* W2 = (const float*)d_in[4];
    const float* b2 = (const float*)d_in[5];
    // d_in[6..9] = Wq,bq,Wk,bk : dead (softmax over length-1 axis == 1)
    const float* Wv = (const float*)d_in[10];
    const float* bv = (const float*)d_in[11];

    int n = in_sizes[0] / FD;
    int e = in_sizes[1] / 2;
    float* outp = (float*)d_out;

    int vec_ok = ((e & 3) == 0) ? 1 : 0;
    int nb  = (n + 255) / 256;
    int e4  = (e + 1023) / 1024;
    int hg_blocks = (n + 127) / 128;
    int sp_blocks = (n + 63) / 64;
    int aggr_blocks = (n + 7) / 8;

    k_zero_sniff<<<nb, 256>>>((const int*)ei, n);                      // 0
    k_count<<<e4, 256>>>(ei, e, n, vec_ok);                            // 1
    k_scan<<<nb, 256>>>(n);                                            // 2
    k_gemm1_fill<<<hg_blocks + e4, 256>>>(x, W1, ei, e, n, vec_ok,
                                          hg_blocks);                  // 3
    k_aggr<<<aggr_blocks, 256>>>(b1, n, 0);                            // 4
    k_hgemm2<<<hg_blocks, 256>>>(W2, n);                               // 5
    k_aggr<<<aggr_blocks, 256>>>(b2, n, 1);                            // 6
    k_hgemm_split<<<sp_blocks, 128>>>(Wv, bv, outp, n);                // 7
}

// round 16
// speedup vs baseline: 1.2684x; 1.0014x over previous
#include <cuda_runtime.h>
#include <cuda_fp16.h>

// AttGCNEncoder: 2x GCNConv(relu) + single-token attention.
// softmax over length-1 axis == 1  =>  output = relu(gcn2) @ Wv + bv.
//
// R16 vs R15 (200.8us): fill's 318-cycle return-atomic chain removed.
// k_count's atomicAdd return value IS the edge's within-segment slot; it is
// stored to g_eoff[] (sequential int4). Fill becomes atomic-free:
// g_col[rowstart[dst] + eoff[i]] = src. g_cursor eliminated.
// GEMMs: mma.sync.m16n8k16 HMMA. gemm1 still hides under fill (merged kernel).

#define FD 64
#define MAXN 100000
#define MAXE 3200000
#define MAXCOL (MAXE + 3 * MAXN + 16)

__device__ int    g_deg[MAXN];
__device__ int    g_rowstart[MAXN];
__device__ float  g_dis[MAXN];
__device__ __align__(16) int g_col[MAXCOL];
__device__ __align__(16) int g_eoff[MAXE + 4];      // per-edge slot within segment
__device__ __align__(16) __half g_h16[MAXN * FD];   // dis-scaled linear out
__device__ __align__(16) __half g_a16[MAXN * FD];   // layer-1 activations
__device__ __align__(16) float  g_acc[MAXN * FD];   // layer-2 activations
__device__ unsigned long long g_bstate[1024];
__device__ int    g_is64;

typedef unsigned long long u64;
typedef unsigned int u32;

// ---------------- helpers ----------------
__device__ __forceinline__ u32 smem_u32(const void* p) {
    u32 a;
    asm("{ .reg .u64 t; cvta.to.shared.u64 t, %1; cvt.u32.u64 %0, t; }"
        : "=r"(a) : "l"(p));
    return a;
}
__device__ __forceinline__ u32 swz(u32 off) { return off ^ ((off >> 3) & 0x70); }
__device__ __forceinline__ u32 pack2(float a, float b) {
    __half2 h = __floats2half2_rn(a, b);
    return *reinterpret_cast<u32*>(&h);
}
__device__ __forceinline__ void ldmA(u32& a0, u32& a1, u32& a2, u32& a3, u32 addr) {
    asm volatile("ldmatrix.sync.aligned.m8n8.x4.shared.b16 {%0,%1,%2,%3}, [%4];"
                 : "=r"(a0), "=r"(a1), "=r"(a2), "=r"(a3) : "r"(addr));
}
__device__ __forceinline__ void ldmB(u32& b0, u32& b1, u32 addr) {
    asm volatile("ldmatrix.sync.aligned.m8n8.x2.trans.shared.b16 {%0,%1}, [%2];"
                 : "=r"(b0), "=r"(b1) : "r"(addr));
}
__device__ __forceinline__ void mma16816(float* c, u32 a0, u32 a1, u32 a2, u32 a3,
                                         u32 b0, u32 b1) {
    asm volatile(
        "mma.sync.aligned.m16n8k16.row.col.f32.f16.f16.f32 "
        "{%0,%1,%2,%3}, {%4,%5,%6,%7}, {%8,%9}, {%0,%1,%2,%3};"
        : "+f"(c[0]), "+f"(c[1]), "+f"(c[2]), "+f"(c[3])
        : "r"(a0), "r"(a1), "r"(a2), "r"(a3), "r"(b0), "r"(b1));
}

// ---------------------------------------------------------------------------
// zero deg + lookback state + dtype sniff
// ---------------------------------------------------------------------------
__global__ void k_zero_sniff(const int* __restrict__ ei32, int n) {
    int i = blockIdx.x * blockDim.x + threadIdx.x;
    if (i < n) g_deg[i] = 0;
    if (i < 1024) g_bstate[i] = 0ull;
    if (i == 0) {
        int acc = 0;
#pragma unroll
        for (int j = 0; j < 16; j++) acc |= ei32[2 * j + 1];
        g_is64 = (acc == 0) ? 1 : 0;
    }
}

// ---------------------------------------------------------------------------
// k_count: 4 edges/thread; atomicAdd return = within-segment slot -> g_eoff
// ---------------------------------------------------------------------------
__global__ void k_count(const void* __restrict__ ei, int e, int n, int vec_ok) {
    int b = (blockIdx.x * blockDim.x + threadIdx.x) * 4;
    if (b >= e) return;
    int d[4];
    if (g_is64) {
        const long long* dst = (const long long*)ei + e;
        if (vec_ok && b + 3 < e) {
            longlong2 p0 = __ldg((const longlong2*)(dst + b));
            longlong2 p1 = __ldg((const longlong2*)(dst + b + 2));
            d[0] = (int)p0.x; d[1] = (int)p0.y; d[2] = (int)p1.x; d[3] = (int)p1.y;
        } else {
#pragma unroll
            for (int k = 0; k < 4; k++) d[k] = (b + k < e) ? (int)dst[b + k] : -1;
        }
    } else {
        const int* dst = (const int*)ei + e;
        if (vec_ok && b + 3 < e) {
            int4 p = __ldg((const int4*)(dst + b));
            d[0] = p.x; d[1] = p.y; d[2] = p.z; d[3] = p.w;
        } else {
#pragma unroll
            for (int k = 0; k < 4; k++) d[k] = (b + k < e) ? dst[b + k] : -1;
        }
    }
    int off[4];
#pragma unroll
    for (int k = 0; k < 4; k++) {
        off[k] = 0;
        if (b + k < e && d[k] >= 0 && d[k] < n)
            off[k] = atomicAdd(&g_deg[d[k]], 1);
    }
    if (vec_ok && b + 3 < e) {
        *(int4*)(g_eoff + b) = make_int4(off[0], off[1], off[2], off[3]);
    } else {
#pragma unroll
        for (int k = 0; k < 4; k++)
            if (b + k < e) g_eoff[b + k] = off[k];
    }
}

// ---------------------------------------------------------------------------
// Single-pass decoupled-lookback scan (proven)
// ---------------------------------------------------------------------------
__global__ void k_scan(int n) {
    __shared__ int s[256];
    __shared__ int s_excl;
    int t = threadIdx.x;
    int i = blockIdx.x * 256 + t;
    int deg = (i < n) ? g_deg[i] : 0;
    int v = (deg + 3) & ~3;
    s[t] = v;
    __syncthreads();
#pragma unroll
    for (int off = 1; off < 256; off <<= 1) {
        int x = (t >= off) ? s[t - off] : 0;
        __syncthreads();
        s[t] += x;
        __syncthreads();
    }
    int blocksum = s[255];
    if (t == 0) {
        int excl = 0;
        if (blockIdx.x > 0) {
            atomicExch(&g_bstate[blockIdx.x], (1ull << 32) | (unsigned)blocksum);
            for (int b = blockIdx.x - 1;;) {
                unsigned long long st;
                do { st = atomicAdd(&g_bstate[b], 0ull); } while ((st >> 32) == 0);
                excl += (int)(unsigned)st;
                if ((st >> 32) == 2) break;
                b--;
            }
        }
        atomicExch(&g_bstate[blockIdx.x], (2ull << 32) | (unsigned)(excl + blocksum));
        s_excl = excl;
    }
    __syncthreads();
    if (i < n) {
        g_rowstart[i] = s_excl + s[t] - v;
        g_dis[i] = rsqrtf((float)(deg + 1));
    }
}

// ---------------------------------------------------------------------------
// fill body: atomic-free. p = rowstart[dst] + eoff[i]; g_col[p] = src.
// ---------------------------------------------------------------------------
__device__ __forceinline__ void fill_body(const void* __restrict__ ei, int e,
                                          int n, int vec_ok, int bid, int tid) {
    int b = (bid * 256 + tid) * 4;
    if (b >= e) return;
    int sI[4], dI[4], oI[4];
    if (g_is64) {
        const long long* src = (const long long*)ei;
        const long long* dst = src + e;
        if (vec_ok && b + 3 < e) {
            longlong2 s0 = __ldg((const longlong2*)(src + b));
            longlong2 s1 = __ldg((const longlong2*)(src + b + 2));
            longlong2 d0 = __ldg((const longlong2*)(dst + b));
            longlong2 d1 = __ldg((const longlong2*)(dst + b + 2));
            sI[0]=(int)s0.x; sI[1]=(int)s0.y; sI[2]=(int)s1.x; sI[3]=(int)s1.y;
            dI[0]=(int)d0.x; dI[1]=(int)d0.y; dI[2]=(int)d1.x; dI[3]=(int)d1.y;
        } else {
#pragma unroll
            for (int k = 0; k < 4; k++) {
                sI[k] = (b + k < e) ? (int)src[b + k] : -1;
                dI[k] = (b + k < e) ? (int)dst[b + k] : -1;
            }
        }
    } else {
        const int* src = (const int*)ei;
        const int* dst = src + e;
        if (vec_ok && b + 3 < e) {
            int4 sp = __ldg((const int4*)(src + b));
            int4 dp = __ldg((const int4*)(dst + b));
            sI[0]=sp.x; sI[1]=sp.y; sI[2]=sp.z; sI[3]=sp.w;
            dI[0]=dp.x; dI[1]=dp.y; dI[2]=dp.z; dI[3]=dp.w;
        } else {
#pragma unroll
            for (int k = 0; k < 4; k++) {
                sI[k] = (b + k < e) ? src[b + k] : -1;
                dI[k] = (b + k < e) ? dst[b + k] : -1;
            }
        }
    }
    if (vec_ok && b + 3 < e) {
        int4 op = *(const int4*)(g_eoff + b);
        oI[0] = op.x; oI[1] = op.y; oI[2] = op.z; oI[3] = op.w;
    } else {
#pragma unroll
        for (int k = 0; k < 4; k++) oI[k] = (b + k < e) ? g_eoff[b + k] : 0;
    }
#pragma unroll
    for (int k = 0; k < 4; k++) {
        if (b + k < e && sI[k] >= 0 && sI[k] < n && dI[k] >= 0 && dI[k] < n) {
            int p = __ldg(&g_rowstart[dI[k]]) + oI[k];
            g_col[p] = sI[k];
        }
    }
}

// ---------------------------------------------------------------------------
// HMMA gemm body: 128 rows/tile, fp16 in, f32 accum,
// epilogue g_h16[r] = fp16(dis[r] * acc).
// ---------------------------------------------------------------------------
__device__ __forceinline__ void hgemm_body(const float* __restrict__ Af32,
                                           const float* __restrict__ W,
                                           int asel, int n, int rowbase,
                                           __half* sA, __half* sB, int tid) {
    char* sAb = (char*)sA;
    char* sBb = (char*)sB;

#pragma unroll
    for (int it = 0; it < 4; it++) {
        int idx = tid + it * 256;
        int r = idx >> 3, c = idx & 7;
        int gr = rowbase + r;
        uint4 v;
        if (gr < n) {
            if (asel) {
                v = __ldg((const uint4*)(g_a16 + (size_t)gr * FD + c * 8));
            } else {
                const float4* s = (const float4*)(Af32 + (size_t)gr * FD + c * 8);
                float4 f0 = __ldg(s), f1 = __ldg(s + 1);
                v.x = pack2(f0.x, f0.y); v.y = pack2(f0.z, f0.w);
                v.z = pack2(f1.x, f1.y); v.w = pack2(f1.z, f1.w);
            }
        } else v = make_uint4(0, 0, 0, 0);
        *(uint4*)(sAb + swz((u32)(r * 128 + c * 16))) = v;
    }
#pragma unroll
    for (int it = 0; it < 2; it++) {
        int idx = tid + it * 256;
        int k = idx >> 3, c = idx & 7;
        const float4* s = (const float4*)(W + (size_t)k * FD + c * 8);
        float4 f0 = __ldg(s), f1 = __ldg(s + 1);
        uint4 v;
        v.x = pack2(f0.x, f0.y); v.y = pack2(f0.z, f0.w);
        v.z = pack2(f1.x, f1.y); v.w = pack2(f1.z, f1.w);
        *(uint4*)(sBb + swz((u32)(k * 128 + c * 16))) = v;
    }
    __syncthreads();

    int lane = tid & 31;
    int warp = tid >> 5;
    u32 baseA = smem_u32(sA);
    u32 baseB = smem_u32(sB);

    u32 a[4][4];
    {
        int r = warp * 16 + (lane & 15);
        int cbyte = (lane >> 4) * 16;
#pragma unroll
        for (int k = 0; k < 4; k++)
            ldmA(a[k][0], a[k][1], a[k][2], a[k][3],
                 baseA + swz((u32)(r * 128 + cbyte + k * 32)));
    }

    float c[8][4];
#pragma unroll
    for (int nt = 0; nt < 8; nt++)
#pragma unroll
        for (int j = 0; j < 4; j++) c[nt][j] = 0.f;

#pragma unroll
    for (int k = 0; k < 4; k++) {
        int br = k * 16 + (lane & 15);
#pragma unroll
        for (int nt = 0; nt < 8; nt++) {
            u32 b0, b1;
            ldmB(b0, b1, baseB + swz((u32)(br * 128 + nt * 16)));
            mma16816(c[nt], a[k][0], a[k][1], a[k][2], a[k][3], b0, b1);
        }
    }

    int gr0 = rowbase + warp * 16 + (lane >> 2);
    int gr1 = gr0 + 8;
    float d0 = (gr0 < n) ? g_dis[gr0] : 0.f;
    float d1 = (gr1 < n) ? g_dis[gr1] : 0.f;
#pragma unroll
    for (int nt = 0; nt < 8; nt++) {
        int col = nt * 8 + (lane & 3) * 2;
        if (gr0 < n)
            *(__half2*)(g_h16 + (size_t)gr0 * FD + col) =
                __floats2half2_rn(d0 * c[nt][0], d0 * c[nt][1]);
        if (gr1 < n)
            *(__half2*)(g_h16 + (size_t)gr1 * FD + col) =
                __floats2half2_rn(d1 * c[nt][2], d1 * c[nt][3]);
    }
}

// ---------------------------------------------------------------------------
// Merged: blocks [0,gb) run gemm1 (x@W1 -> g_h16); rest run atomic-free fill.
// ---------------------------------------------------------------------------
__global__ __launch_bounds__(256) void k_gemm1_fill(const float* __restrict__ x,
                                                    const float* __restrict__ W1,
                                                    const void* __restrict__ ei,
                                                    int e, int n, int vec_ok,
                                                    int gb) {
    __shared__ __align__(1024) __half sA[128 * FD];
    __shared__ __align__(1024) __half sB[FD * FD];
    if ((int)blockIdx.x < gb) {
        hgemm_body(x, W1, 0, n, blockIdx.x * 128, sA, sB, threadIdx.x);
    } else {
        fill_body(ei, e, n, vec_ok, blockIdx.x - gb, threadIdx.x);
    }
}

__global__ __launch_bounds__(256) void k_hgemm2(const float* __restrict__ W, int n) {
    __shared__ __align__(1024) __half sA[128 * FD];
    __shared__ __align__(1024) __half sB[FD * FD];
    hgemm_body(nullptr, W, 1, n, blockIdx.x * 128, sA, sB, threadIdx.x);
}

// ---------------------------------------------------------------------------
// Final Wv GEMM, hi/lo fp16 split: D = Ah@Wh + Al@Wh + Ah@Wl (+bias)
// ---------------------------------------------------------------------------
__global__ __launch_bounds__(128) void k_hgemm_split(const float* __restrict__ W,
                                                     const float* __restrict__ bias,
                                                     float* __restrict__ outf, int n) {
    __shared__ __align__(1024) __half sAh[64 * FD];
    __shared__ __align__(1024) __half sAl[64 * FD];
    __shared__ __align__(1024) __half sBh[FD * FD];
    __shared__ __align__(1024) __half sBl[FD * FD];

    int tid = threadIdx.x;
    int rowbase = blockIdx.x * 64;
    char *sAhb = (char*)sAh, *sAlb = (char*)sAl;
    char *sBhb = (char*)sBh, *sBlb = (char*)sBl;

#pragma unroll
    for (int it = 0; it < 4; it++) {
        int idx = tid + it * 128;
        int r = idx >> 3, c = idx & 7;
        int gr = rowbase + r;
        uint4 vh = make_uint4(0,0,0,0), vl = make_uint4(0,0,0,0);
        if (gr < n) {
            const float4* s = (const float4*)(g_acc + (size_t)gr * FD + c * 8);
            float4 f0 = __ldg(s), f1 = __ldg(s + 1);
            float f[8] = {f0.x,f0.y,f0.z,f0.w,f1.x,f1.y,f1.z,f1.w};
            u32 ph[4], pl[4];
#pragma unroll
            for (int q = 0; q < 4; q++) {
                __half h0 = __float2half_rn(f[2*q]);
                __half h1 = __float2half_rn(f[2*q+1]);
                __half l0 = __float2half_rn(f[2*q]   - __half2float(h0));
                __half l1 = __float2half_rn(f[2*q+1] - __half2float(h1));
                __half2 hh = __halves2half2(h0, h1);
                __half2 ll = __halves2half2(l0, l1);
                ph[q] = *reinterpret_cast<u32*>(&hh);
                pl[q] = *reinterpret_cast<u32*>(&ll);
            }
            vh = make_uint4(ph[0], ph[1], ph[2], ph[3]);
            vl = make_uint4(pl[0], pl[1], pl[2], pl[3]);
        }
        u32 off = swz((u32)(r * 128 + c * 16));
        *(uint4*)(sAhb + off) = vh;
        *(uint4*)(sAlb + off) = vl;
    }
#pragma unroll
    for (int it = 0; it < 4; it++) {
        int idx = tid + it * 128;
        int k = idx >> 3, c = idx & 7;
        const float4* s = (const float4*)(W + (size_t)k * FD + c * 8);
        float4 f0 = __ldg(s), f1 = __ldg(s + 1);
        float f[8] = {f0.x,f0.y,f0.z,f0.w,f1.x,f1.y,f1.z,f1.w};
        u32 ph[4], pl[4];
#pragma unroll
        for (int q = 0; q < 4; q++) {
            __half h0 = __float2half_rn(f[2*q]);
            __half h1 = __float2half_rn(f[2*q+1]);
            __half l0 = __float2half_rn(f[2*q]   - __half2float(h0));
            __half l1 = __float2half_rn(f[2*q+1] - __half2float(h1));
            __half2 hh = __halves2half2(h0, h1);
            __half2 ll = __halves2half2(l0, l1);
            ph[q] = *reinterpret_cast<u32*>(&hh);
            pl[q] = *reinterpret_cast<u32*>(&ll);
        }
        u32 off = swz((u32)(k * 128 + c * 16));
        *(uint4*)(sBhb + off) = make_uint4(ph[0], ph[1], ph[2], ph[3]);
        *(uint4*)(sBlb + off) = make_uint4(pl[0], pl[1], pl[2], pl[3]);
    }
    __syncthreads();

    int lane = tid & 31;
    int warp = tid >> 5;
    u32 bAh = smem_u32(sAh), bAl = smem_u32(sAl);
    u32 bBh = smem_u32(sBh), bBl = smem_u32(sBl);

    u32 ah[4][4], al[4][4];
    {
        int r = warp * 16 + (lane & 15);
        int cbyte = (lane >> 4) * 16;
#pragma unroll
        for (int k = 0; k < 4; k++) {
            u32 off = swz((u32)(r * 128 + cbyte + k * 32));
            ldmA(ah[k][0], ah[k][1], ah[k][2], ah[k][3], bAh + off);
            ldmA(al[k][0], al[k][1], al[k][2], al[k][3], bAl + off);
        }
    }

    float c[8][4];
#pragma unroll
    for (int nt = 0; nt < 8; nt++)
#pragma unroll
        for (int j = 0; j < 4; j++) c[nt][j] = 0.f;

#pragma unroll
    for (int k = 0; k < 4; k++) {
        int br = k * 16 + (lane & 15);
#pragma unroll
        for (int nt = 0; nt < 8; nt++) {
            u32 off = swz((u32)(br * 128 + nt * 16));
            u32 bh0, bh1, bl0, bl1;
            ldmB(bh0, bh1, bBh + off);
            ldmB(bl0, bl1, bBl + off);
            mma16816(c[nt], ah[k][0], ah[k][1], ah[k][2], ah[k][3], bh0, bh1);
            mma16816(c[nt], al[k][0], al[k][1], al[k][2], al[k][3], bh0, bh1);
            mma16816(c[nt], ah[k][0], ah[k][1], ah[k][2], ah[k][3], bl0, bl1);
        }
    }

    int gr0 = rowbase + warp * 16 + (lane >> 2);
    int gr1 = gr0 + 8;
#pragma unroll
    for (int nt = 0; nt < 8; nt++) {
        int col = nt * 8 + (lane & 3) * 2;
        float bx = bias[col], by = bias[col + 1];
        if (gr0 < n)
            *(float2*)(outf + (size_t)gr0 * FD + col) =
                make_float2(c[nt][0] + bx, c[nt][1] + by);
        if (gr1 < n)
            *(float2*)(outf + (size_t)gr1 * FD + col) =
                make_float2(c[nt][2] + bx, c[nt][3] + by);
    }
}

// ---------------------------------------------------------------------------
// GCN aggregation: warp per dst node; aligned-int4 col reads.
// mode 0 -> write fp16 g_a16 ; mode 1 -> write fp32 g_acc
// ---------------------------------------------------------------------------
__global__ void k_aggr(const float* __restrict__ bias, int n, int mode) {
    int i = (blockIdx.x * blockDim.x + threadIdx.x) >> 5;
    int lane = threadIdx.x & 31;
    if (i >= n) return;

    const __half2* h2 = (const __half2*)g_h16;
    float2 self = __half22float2(h2[i * 32 + lane]);
    float ax = self.x, ay = self.y;

    int start = g_rowstart[i];
    int len   = g_deg[i];
    const int4* c4 = (const int4*)(g_col + start);
    int nf = len >> 2;
#pragma unroll 2
    for (int q = 0; q < nf; q++) {
        int4 cc = __ldg(&c4[q]);
        float2 v0 = __half22float2(__ldg(&h2[cc.x * 32 + lane]));
        float2 v1 = __half22float2(__ldg(&h2[cc.y * 32 + lane]));
        float2 v2 = __half22float2(__ldg(&h2[cc.z * 32 + lane]));
        float2 v3 = __half22float2(__ldg(&h2[cc.w * 32 + lane]));
        ax += (v0.x + v1.x) + (v2.x + v3.x);
        ay += (v0.y + v1.y) + (v2.y + v3.y);
    }
    for (int j = nf * 4; j < len; j++) {
        int s = __ldg(&g_col[start + j]);
        float2 v = __half22float2(__ldg(&h2[s * 32 + lane]));
        ax += v.x;
        ay += v.y;
    }

    float di = g_dis[i];
    float bx = bias[2 * lane], by = bias[2 * lane + 1];
    ax = fmaxf(fmaf(di, ax, bx), 0.f);
    ay = fmaxf(fmaf(di, ay, by), 0.f);
    if (mode == 0)
        ((__half2*)g_a16)[i * 32 + lane] = __floats2half2_rn(ax, ay);
    else
        ((float2*)g_acc)[i * 32 + lane] = make_float2(ax, ay);
}

// ---------------------------------------------------------------------------
// Launch — kernel launches ONLY (graph-capture-safe)
// ---------------------------------------------------------------------------
extern "C" void kernel_launch(void* const* d_in, const int* in_sizes, int n_in,
                              void* d_out, int out_size) {
    const float* x  = (const float*)d_in[0];
    const void*  ei = d_in[1];
    const float* W1 = (const float*)d_in[2];
    const float* b1 = (const float*)d_in[3];
    const float* W2 = (const float*)d_in[4];
    const float* b2 = (const float*)d_in[5];
    // d_in[6..9] = Wq,bq,Wk,bk : dead (softmax over length-1 axis == 1)
    const float* Wv = (const float*)d_in[10];
    const float* bv = (const float*)d_in[11];

    int n = in_sizes[0] / FD;
    int e = in_sizes[1] / 2;
    float* outp = (float*)d_out;

    int vec_ok = ((e & 3) == 0) ? 1 : 0;
    int nb  = (n + 255) / 256;
    int e4  = (e + 1023) / 1024;
    int hg_blocks = (n + 127) / 128;
    int sp_blocks = (n + 63) / 64;
    int aggr_blocks = (n + 7) / 8;

    k_zero_sniff<<<nb, 256>>>((const int*)ei, n);                      // 0
    k_count<<<e4, 256>>>(ei, e, n, vec_ok);                            // 1
    k_scan<<<nb, 256>>>(n);                                            // 2
    k_gemm1_fill<<<hg_blocks + e4, 256>>>(x, W1, ei, e, n, vec_ok,
                                          hg_blocks);                  // 3
    k_aggr<<<aggr_blocks, 256>>>(b1, n, 0);                            // 4
    k_hgemm2<<<hg_blocks, 256>>>(W2, n);                               // 5
    k_aggr<<<aggr_blocks, 256>>>(b2, n, 1);                            // 6
    k_hgemm_split<<<sp_blocks, 128>>>(Wv, bv, outp, n);                // 7
}